// round 9
// baseline (speedup 1.0000x reference)
#include <cuda_runtime.h>
#include <cstddef>
#include <cstdint>

#define BATCH 2
#define NSEQ  2048
#define DIM   1024
#define NH    16
#define DH    64
#define MTOK  (BATCH * NSEQ)   // 4096

// Scratch (allocation-free rule: __device__ globals). All [bh][s][d] layout.
__device__ float g_Q[BATCH * NH * NSEQ * DH];   // tf32 bits, pre-scaled by 1/8
__device__ float g_K[BATCH * NH * NSEQ * DH];   // tf32 bits
__device__ float g_V[BATCH * NH * NSEQ * DH];   // tf32 bits
__device__ float g_A[BATCH * NSEQ * DIM];       // attention out fp32, [b][q][h*64+d]

// ---------------------------------------------------------------------------
__device__ __forceinline__ uint32_t f2tf32(float x) {
    uint32_t y;
    asm("cvt.rna.tf32.f32 %0, %1;" : "=r"(y) : "f"(x));
    return y;
}

__device__ __forceinline__ float4 cvt4(float4 v) {
    return make_float4(__uint_as_float(f2tf32(v.x)), __uint_as_float(f2tf32(v.y)),
                       __uint_as_float(f2tf32(v.z)), __uint_as_float(f2tf32(v.w)));
}

__device__ __forceinline__ uint32_t cvta_smem(const void* p) {
    uint32_t a;
    asm("{ .reg .u64 t; cvta.to.shared.u64 t, %1; cvt.u32.u64 %0, t; }"
        : "=r"(a) : "l"(p));
    return a;
}

// ldmatrix x4: four 8x8 b16 matrices == four 8x4 b32 (tf32) fragments
__device__ __forceinline__ void ldsm4(uint32_t* r, uint32_t addr) {
    asm volatile("ldmatrix.sync.aligned.m8n8.x4.shared.b16 {%0,%1,%2,%3}, [%4];"
                 : "=r"(r[0]), "=r"(r[1]), "=r"(r[2]), "=r"(r[3]) : "r"(addr));
}

// D += A * B, m16n8k8 tf32 (A row-major 16x8, B col-major 8x8)
__device__ __forceinline__ void mma8(float* d, const uint32_t* a, const uint32_t* b) {
    asm volatile(
        "mma.sync.aligned.m16n8k8.row.col.f32.tf32.tf32.f32 "
        "{%0,%1,%2,%3}, {%4,%5,%6,%7}, {%8,%9}, {%0,%1,%2,%3};"
        : "+f"(d[0]), "+f"(d[1]), "+f"(d[2]), "+f"(d[3])
        : "r"(a[0]), "r"(a[1]), "r"(a[2]), "r"(a[3]), "r"(b[0]), "r"(b[1]));
}

// ---------------------------------------------------------------------------
// tf32 tensor-core GEMM: C = A @ W^T. (unchanged from R7)
// ---------------------------------------------------------------------------
template <int LAYOUT>
__global__ __launch_bounds__(256)
void tgemm(const float* __restrict__ A, const float* __restrict__ W,
           const float* __restrict__ bias, float* __restrict__ C, float scale)
{
    __shared__ float As[2][128][20];
    __shared__ float Bs[2][128][20];

    const int tid = threadIdx.x;
    const int lane = tid & 31, wid = tid >> 5;
    const int g = lane >> 2, tq = lane & 3;
    const int wm = (wid & 3) * 32, wn = (wid >> 2) * 64;
    const int m0 = blockIdx.y * 128, n0 = blockIdx.x * 128;

    const int lrA = lane & 15;
    const int lcA = (lane >> 4) * 4;
    const int lrB = (lane & 7) + ((lane >> 4) << 3);
    const int lcB = ((lane >> 3) & 1) * 4;

    const uint32_t As_b = cvta_smem(&As[0][0][0]);
    const uint32_t Bs_b = cvta_smem(&Bs[0][0][0]);
    const uint32_t aA = As_b + (uint32_t)(wm + lrA) * 80u + (uint32_t)lcA * 4u;
    const uint32_t aB = Bs_b + (uint32_t)(wn + lrB) * 80u + (uint32_t)lcB * 4u;

    const int lr = tid >> 1;
    const int lc = (tid & 1) * 8;
    const float* Ap = A + (size_t)(m0 + lr) * DIM + lc;
    const float* Wp = W + (size_t)(n0 + lr) * DIM + lc;

    float acc[2][8][4];
#pragma unroll
    for (int mt = 0; mt < 2; mt++)
#pragma unroll
        for (int nt = 0; nt < 8; nt++)
#pragma unroll
            for (int c = 0; c < 4; c++) acc[mt][nt][c] = 0.f;

    {
        float4 a0 = *(const float4*)Ap, a1 = *(const float4*)(Ap + 4);
        float4 b0 = *(const float4*)Wp, b1 = *(const float4*)(Wp + 4);
        *(float4*)&As[0][lr][lc]     = cvt4(a0);
        *(float4*)&As[0][lr][lc + 4] = cvt4(a1);
        *(float4*)&Bs[0][lr][lc]     = cvt4(b0);
        *(float4*)&Bs[0][lr][lc + 4] = cvt4(b1);
    }
    __syncthreads();

    for (int kt = 0; kt < 64; kt++) {
        const uint32_t bo = (kt & 1) ? 10240u : 0u;
        float4 pa0, pa1, pb0, pb1;
        if (kt < 63) {
            const float* s1 = Ap + (kt + 1) * 16;
            const float* s2 = Wp + (kt + 1) * 16;
            pa0 = *(const float4*)s1; pa1 = *(const float4*)(s1 + 4);
            pb0 = *(const float4*)s2; pb1 = *(const float4*)(s2 + 4);
        }
#pragma unroll
        for (int kc = 0; kc < 2; kc++) {
            uint32_t af[2][4], bf[4][4];
            ldsm4(af[0], aA + bo + kc * 32u);
            ldsm4(af[1], aA + bo + 1280u + kc * 32u);
#pragma unroll
            for (int p = 0; p < 4; p++)
                ldsm4(bf[p], aB + bo + (uint32_t)p * 1280u + kc * 32u);
#pragma unroll
            for (int mt = 0; mt < 2; mt++)
#pragma unroll
                for (int p = 0; p < 4; p++) {
                    mma8(acc[mt][2 * p],     af[mt], &bf[p][0]);
                    mma8(acc[mt][2 * p + 1], af[mt], &bf[p][2]);
                }
        }
        if (kt < 63) {
            const uint32_t nxt = (kt & 1) ^ 1;
            *(float4*)&As[nxt][lr][lc]     = cvt4(pa0);
            *(float4*)&As[nxt][lr][lc + 4] = cvt4(pa1);
            *(float4*)&Bs[nxt][lr][lc]     = cvt4(pb0);
            *(float4*)&Bs[nxt][lr][lc + 4] = cvt4(pb1);
        }
        __syncthreads();
    }

#pragma unroll
    for (int mt = 0; mt < 2; mt++) {
        const int r0 = m0 + wm + mt * 16 + g;
        const int r1 = r0 + 8;
#pragma unroll
        for (int nt = 0; nt < 8; nt++) {
            const int n = n0 + wn + nt * 8 + tq * 2;
            if (LAYOUT == 0) {
                const float b0v = bias[n], b1v = bias[n + 1];
                float2 v0 = make_float2(acc[mt][nt][0] + b0v, acc[mt][nt][1] + b1v);
                float2 v1 = make_float2(acc[mt][nt][2] + b0v, acc[mt][nt][3] + b1v);
                *(float2*)&C[(size_t)r0 * DIM + n] = v0;
                *(float2*)&C[(size_t)r1 * DIM + n] = v1;
            } else {
                const int h = n >> 6, d = n & 63;
                const int b0i = r0 >> 11, s0 = r0 & (NSEQ - 1);
                const int b1i = r1 >> 11, s1 = r1 & (NSEQ - 1);
                float2 v0 = make_float2(
                    __uint_as_float(f2tf32(acc[mt][nt][0] * scale)),
                    __uint_as_float(f2tf32(acc[mt][nt][1] * scale)));
                float2 v1 = make_float2(
                    __uint_as_float(f2tf32(acc[mt][nt][2] * scale)),
                    __uint_as_float(f2tf32(acc[mt][nt][3] * scale)));
                *(float2*)&C[((size_t)(b0i * NH + h) * NSEQ + s0) * DH + d] = v0;
                *(float2*)&C[((size_t)(b1i * NH + h) * NSEQ + s1) * DH + d] = v1;
            }
        }
    }
}

// ---------------------------------------------------------------------------
// Flash attention on tensor cores. Bq=128 (4 warps x 2 m-tiles), Bk=64, Dh=64.
// All fragments (Q, K, P, V) via ldmatrix. V staged transposed (Vt[d][kv]).
// No Q-register hoist (register pressure); Q re-read from SMEM each tile.
// ---------------------------------------------------------------------------
#define AQ  0                    // Qs: [128][68] = 8704 floats
#define AP  8704                 // Ps: [128][68]
#define AK  17408                // Ks: [64][68]  = 4352
#define AV  21760                // Vt: [64][68]  (transposed: rows=d, cols=kv)
#define AM  26112                // mask: 64 ints
#define ATTN_SMEM_BYTES ((26112 + 64) * 4)   // 104704

__global__ __launch_bounds__(128)
void attn_kernel(const float* __restrict__ Qg, const float* __restrict__ Kg,
                 const float* __restrict__ Vg, const int* __restrict__ mask,
                 float* __restrict__ Og)
{
    extern __shared__ float sm[];
    float* Qs = sm + AQ;
    float* Ps = sm + AP;
    float* Ks = sm + AK;
    float* Vt = sm + AV;
    int*   mk = (int*)(sm + AM);

    const int tid = threadIdx.x;
    const int lane = tid & 31, w = tid >> 5;
    const int g = lane >> 2, tq = lane & 3;
    const int bh = blockIdx.y;
    const int b = bh >> 4, h = bh & 15;
    const int q0 = blockIdx.x * 128;

    // ldmatrix per-lane mappings (row stride 68 floats = 272 bytes)
    const int lrA = lane & 15;
    const int lcA = (lane >> 4) * 4;
    const int lrB = (lane & 7) + ((lane >> 4) << 3);
    const int lcB = ((lane >> 3) & 1) * 4;
    const uint32_t pQ = cvta_smem(Qs) + (uint32_t)(w * 32 + lrA) * 272u + (uint32_t)lcA * 4u;
    const uint32_t pP = cvta_smem(Ps) + (uint32_t)(w * 32 + lrA) * 272u + (uint32_t)lcA * 4u;
    const uint32_t pK = cvta_smem(Ks) + (uint32_t)lrB * 272u + (uint32_t)lcB * 4u;
    const uint32_t pV = cvta_smem(Vt) + (uint32_t)lrB * 272u + (uint32_t)lcB * 4u;

    // stage Q tile (contiguous 128x64 block) into padded smem
    {
        const float* Qb = Qg + ((size_t)bh * NSEQ + q0) * DH;
#pragma unroll
        for (int it = 0; it < 16; it++) {
            int j = it * 128 + tid;
            *(float4*)&Qs[(j >> 4) * 68 + (j & 15) * 4] = *(const float4*)(Qb + j * 4);
        }
    }

    const int rb[2] = { w * 32 + g, w * 32 + 16 + g };

    float m_[2][2], l_[2][2], o[2][8][4];
#pragma unroll
    for (int mt = 0; mt < 2; mt++) {
        m_[mt][0] = -1e30f; m_[mt][1] = -1e30f;
        l_[mt][0] = 0.f;    l_[mt][1] = 0.f;
#pragma unroll
        for (int nt = 0; nt < 8; nt++)
#pragma unroll
            for (int c = 0; c < 4; c++) o[mt][nt][c] = 0.f;
    }

    for (int t = 0; t < NSEQ / 64; t++) {
        const int kv0 = t * 64;
        __syncthreads();
        {
            const float* Kb = Kg + ((size_t)bh * NSEQ + kv0) * DH;
            const float* Vb = Vg + ((size_t)bh * NSEQ + kv0) * DH;
            // K: rows = kv, direct copy
#pragma unroll
            for (int it = 0; it < 8; it++) {
                int j = it * 128 + tid;
                *(float4*)&Ks[(j >> 4) * 68 + (j & 15) * 4] = *(const float4*)(Kb + j * 4);
            }
            // V: transposed store, 4x4 blocks (rows=d, cols=kv)
            const int c0 = 4 * (tid & 15);       // d block
#pragma unroll
            for (int ii = 0; ii < 2; ii++) {
                const int r0 = 4 * ((tid >> 4) + 8 * ii);   // kv block
                float4 i0 = *(const float4*)&Vb[(r0 + 0) * DH + c0];
                float4 i1 = *(const float4*)&Vb[(r0 + 1) * DH + c0];
                float4 i2 = *(const float4*)&Vb[(r0 + 2) * DH + c0];
                float4 i3 = *(const float4*)&Vb[(r0 + 3) * DH + c0];
                *(float4*)&Vt[(c0 + 0) * 68 + r0] = make_float4(i0.x, i1.x, i2.x, i3.x);
                *(float4*)&Vt[(c0 + 1) * 68 + r0] = make_float4(i0.y, i1.y, i2.y, i3.y);
                *(float4*)&Vt[(c0 + 2) * 68 + r0] = make_float4(i0.z, i1.z, i2.z, i3.z);
                *(float4*)&Vt[(c0 + 3) * 68 + r0] = make_float4(i0.w, i1.w, i2.w, i3.w);
            }
            if (tid < 64) mk[tid] = mask[b * NSEQ + kv0 + tid];
        }
        __syncthreads();

        // S = Q @ K^T  (2 x 16 q-rows per warp x 64 kv)
        float s[2][8][4];
#pragma unroll
        for (int mt = 0; mt < 2; mt++)
#pragma unroll
            for (int nt = 0; nt < 8; nt++)
#pragma unroll
                for (int c = 0; c < 4; c++) s[mt][nt][c] = 0.f;

#pragma unroll
        for (int kc = 0; kc < 8; kc++) {
            uint32_t af[2][4], kf[4][4];
            ldsm4(af[0], pQ + (uint32_t)kc * 32u);
            ldsm4(af[1], pQ + 4352u + (uint32_t)kc * 32u);
#pragma unroll
            for (int p = 0; p < 4; p++)
                ldsm4(kf[p], pK + (uint32_t)p * 4352u + (uint32_t)kc * 32u);
#pragma unroll
            for (int mt = 0; mt < 2; mt++)
#pragma unroll
                for (int p = 0; p < 4; p++) {
                    mma8(s[mt][2 * p],     af[mt], &kf[p][0]);
                    mma8(s[mt][2 * p + 1], af[mt], &kf[p][2]);
                }
        }

        // mask (per kv column)
#pragma unroll
        for (int nt = 0; nt < 8; nt++) {
            const int j = nt * 8 + tq * 2;
            const int mv0 = mk[j], mv1 = mk[j + 1];
#pragma unroll
            for (int mt = 0; mt < 2; mt++) {
                if (!mv0) { s[mt][nt][0] = -1e9f; s[mt][nt][2] = -1e9f; }
                if (!mv1) { s[mt][nt][1] = -1e9f; s[mt][nt][3] = -1e9f; }
            }
        }

        // online softmax (per m-tile, rows g and g+8; reduce across quad lanes)
#pragma unroll
        for (int mt = 0; mt < 2; mt++) {
            float rm0 = -1e30f, rm1 = -1e30f;
#pragma unroll
            for (int nt = 0; nt < 8; nt++) {
                rm0 = fmaxf(rm0, fmaxf(s[mt][nt][0], s[mt][nt][1]));
                rm1 = fmaxf(rm1, fmaxf(s[mt][nt][2], s[mt][nt][3]));
            }
            rm0 = fmaxf(rm0, __shfl_xor_sync(0xffffffffu, rm0, 1));
            rm0 = fmaxf(rm0, __shfl_xor_sync(0xffffffffu, rm0, 2));
            rm1 = fmaxf(rm1, __shfl_xor_sync(0xffffffffu, rm1, 1));
            rm1 = fmaxf(rm1, __shfl_xor_sync(0xffffffffu, rm1, 2));
            const float mn0 = fmaxf(m_[mt][0], rm0), mn1 = fmaxf(m_[mt][1], rm1);
            const float al0 = __expf(m_[mt][0] - mn0), al1 = __expf(m_[mt][1] - mn1);
            float rs0 = 0.f, rs1 = 0.f;
#pragma unroll
            for (int nt = 0; nt < 8; nt++) {
                s[mt][nt][0] = __expf(s[mt][nt][0] - mn0);
                s[mt][nt][1] = __expf(s[mt][nt][1] - mn0);
                s[mt][nt][2] = __expf(s[mt][nt][2] - mn1);
                s[mt][nt][3] = __expf(s[mt][nt][3] - mn1);
                rs0 += s[mt][nt][0] + s[mt][nt][1];
                rs1 += s[mt][nt][2] + s[mt][nt][3];
            }
            rs0 += __shfl_xor_sync(0xffffffffu, rs0, 1);
            rs0 += __shfl_xor_sync(0xffffffffu, rs0, 2);
            rs1 += __shfl_xor_sync(0xffffffffu, rs1, 1);
            rs1 += __shfl_xor_sync(0xffffffffu, rs1, 2);
            l_[mt][0] = l_[mt][0] * al0 + rs0;  m_[mt][0] = mn0;
            l_[mt][1] = l_[mt][1] * al1 + rs1;  m_[mt][1] = mn1;
#pragma unroll
            for (int nt = 0; nt < 8; nt++) {
                o[mt][nt][0] *= al0; o[mt][nt][1] *= al0;
                o[mt][nt][2] *= al1; o[mt][nt][3] *= al1;
            }
        }

        // write P (tf32) to warp-private rows of Ps
#pragma unroll
        for (int mt = 0; mt < 2; mt++)
#pragma unroll
            for (int nt = 0; nt < 8; nt++) {
                const int j = nt * 8 + tq * 2;
                float2 p0 = make_float2(__uint_as_float(f2tf32(s[mt][nt][0])),
                                        __uint_as_float(f2tf32(s[mt][nt][1])));
                float2 p1 = make_float2(__uint_as_float(f2tf32(s[mt][nt][2])),
                                        __uint_as_float(f2tf32(s[mt][nt][3])));
                *(float2*)&Ps[(rb[mt]    ) * 68 + j] = p0;
                *(float2*)&Ps[(rb[mt] + 8) * 68 + j] = p1;
            }
        __syncwarp();

        // O += P @ V   (k = 64 kv, n = 64 d), V fragments via ldmatrix on Vt
#pragma unroll
        for (int kc = 0; kc < 8; kc++) {
            uint32_t af[2][4], vf[4][4];
            ldsm4(af[0], pP + (uint32_t)kc * 32u);
            ldsm4(af[1], pP + 4352u + (uint32_t)kc * 32u);
#pragma unroll
            for (int p = 0; p < 4; p++)
                ldsm4(vf[p], pV + (uint32_t)p * 4352u + (uint32_t)kc * 32u);
#pragma unroll
            for (int mt = 0; mt < 2; mt++)
#pragma unroll
                for (int p = 0; p < 4; p++) {
                    mma8(o[mt][2 * p],     af[mt], &vf[p][0]);
                    mma8(o[mt][2 * p + 1], af[mt], &vf[p][2]);
                }
        }
    }

    // final normalize + store
#pragma unroll
    for (int mt = 0; mt < 2; mt++) {
        const float inv0 = 1.f / l_[mt][0], inv1 = 1.f / l_[mt][1];
        const int qr0 = q0 + rb[mt], qr1 = qr0 + 8;
#pragma unroll
        for (int nt = 0; nt < 8; nt++) {
            const int d = nt * 8 + tq * 2;
            float2 v0 = make_float2(o[mt][nt][0] * inv0, o[mt][nt][1] * inv0);
            float2 v1 = make_float2(o[mt][nt][2] * inv1, o[mt][nt][3] * inv1);
            *(float2*)&Og[(size_t)(b * NSEQ + qr0) * DIM + h * DH + d] = v0;
            *(float2*)&Og[(size_t)(b * NSEQ + qr1) * DIM + h * DH + d] = v1;
        }
    }
}

// ---------------------------------------------------------------------------
extern "C" void kernel_launch(void* const* d_in, const int* in_sizes, int n_in,
                              void* d_out, int out_size)
{
    const float* x1 = (const float*)d_in[0];   // feat1_query
    const float* x2 = (const float*)d_in[1];   // feat2_key_value
    const float* Wq = (const float*)d_in[2];
    const float* Wk = (const float*)d_in[3];
    const float* Wv = (const float*)d_in[4];
    const float* Wo = (const float*)d_in[5];
    const float* bo = (const float*)d_in[6];
    const int*   mk = (const int*)d_in[7];
    float* out = (float*)d_out;

    float *q, *k, *v, *a;
    cudaGetSymbolAddress((void**)&q, g_Q);
    cudaGetSymbolAddress((void**)&k, g_K);
    cudaGetSymbolAddress((void**)&v, g_V);
    cudaGetSymbolAddress((void**)&a, g_A);

    const dim3 gg(DIM / 128, MTOK / 128);   // (8, 32)
    tgemm<2><<<gg, 256>>>(x1, Wq, nullptr, q, 0.125f);
    tgemm<2><<<gg, 256>>>(x2, Wk, nullptr, k, 1.0f);
    tgemm<2><<<gg, 256>>>(x2, Wv, nullptr, v, 1.0f);

    cudaFuncSetAttribute(attn_kernel, cudaFuncAttributeMaxDynamicSharedMemorySize,
                         ATTN_SMEM_BYTES);
    attn_kernel<<<dim3(NSEQ / 128, BATCH * NH), 128, ATTN_SMEM_BYTES>>>(q, k, v, mk, a);

    tgemm<0><<<gg, 256>>>(a, Wo, bo, out, 1.0f);
}

// round 12
// speedup vs baseline: 1.0728x; 1.0728x over previous
#include <cuda_runtime.h>
#include <cstddef>
#include <cstdint>

#define BATCH 2
#define NSEQ  2048
#define DIM   1024
#define NH    16
#define DH    64
#define MTOK  (BATCH * NSEQ)   // 4096

// Scratch (allocation-free rule: __device__ globals). All [bh][s][d] layout.
__device__ float g_Q[BATCH * NH * NSEQ * DH];   // tf32 bits, pre-scaled by 1/8
__device__ float g_K[BATCH * NH * NSEQ * DH];   // tf32 bits
__device__ float g_V[BATCH * NH * NSEQ * DH];   // tf32 bits
__device__ float g_A[BATCH * NSEQ * DIM];       // attention out fp32, [b][q][h*64+d]

// ---------------------------------------------------------------------------
__device__ __forceinline__ uint32_t f2tf32(float x) {
    uint32_t y;
    asm("cvt.rna.tf32.f32 %0, %1;" : "=r"(y) : "f"(x));
    return y;
}

__device__ __forceinline__ float4 cvt4(float4 v) {
    return make_float4(__uint_as_float(f2tf32(v.x)), __uint_as_float(f2tf32(v.y)),
                       __uint_as_float(f2tf32(v.z)), __uint_as_float(f2tf32(v.w)));
}

__device__ __forceinline__ uint32_t cvta_smem(const void* p) {
    uint32_t a;
    asm("{ .reg .u64 t; cvta.to.shared.u64 t, %1; cvt.u32.u64 %0, t; }"
        : "=r"(a) : "l"(p));
    return a;
}

// ldmatrix x4: four 8x8 b16 matrices == four 8x4 b32 (tf32) fragments
__device__ __forceinline__ void ldsm4(uint32_t* r, uint32_t addr) {
    asm volatile("ldmatrix.sync.aligned.m8n8.x4.shared.b16 {%0,%1,%2,%3}, [%4];"
                 : "=r"(r[0]), "=r"(r[1]), "=r"(r[2]), "=r"(r[3]) : "r"(addr));
}

// D += A * B, m16n8k8 tf32 (A row-major 16x8, B col-major 8x8)
__device__ __forceinline__ void mma8(float* d, const uint32_t* a, const uint32_t* b) {
    asm volatile(
        "mma.sync.aligned.m16n8k8.row.col.f32.tf32.tf32.f32 "
        "{%0,%1,%2,%3}, {%4,%5,%6,%7}, {%8,%9}, {%0,%1,%2,%3};"
        : "+f"(d[0]), "+f"(d[1]), "+f"(d[2]), "+f"(d[3])
        : "r"(a[0]), "r"(a[1]), "r"(a[2]), "r"(a[3]), "r"(b[0]), "r"(b[1]));
}

// ---------------------------------------------------------------------------
// tf32 tensor-core GEMM: C = A @ W^T.  (R7 version — 337us measured)
// M=4096, N=K=1024. Block 128x128, BK=16 double-buffered, 8 warps (32x64 each).
// Fragment loads via ldmatrix.x4.
// ---------------------------------------------------------------------------
template <int LAYOUT>
__global__ __launch_bounds__(256)
void tgemm(const float* __restrict__ A, const float* __restrict__ W,
           const float* __restrict__ bias, float* __restrict__ C, float scale)
{
    __shared__ float As[2][128][20];
    __shared__ float Bs[2][128][20];

    const int tid = threadIdx.x;
    const int lane = tid & 31, wid = tid >> 5;
    const int g = lane >> 2, tq = lane & 3;
    const int wm = (wid & 3) * 32, wn = (wid >> 2) * 64;
    const int m0 = blockIdx.y * 128, n0 = blockIdx.x * 128;

    const int lrA = lane & 15;
    const int lcA = (lane >> 4) * 4;
    const int lrB = (lane & 7) + ((lane >> 4) << 3);
    const int lcB = ((lane >> 3) & 1) * 4;

    const uint32_t As_b = cvta_smem(&As[0][0][0]);
    const uint32_t Bs_b = cvta_smem(&Bs[0][0][0]);
    const uint32_t aA = As_b + (uint32_t)(wm + lrA) * 80u + (uint32_t)lcA * 4u;
    const uint32_t aB = Bs_b + (uint32_t)(wn + lrB) * 80u + (uint32_t)lcB * 4u;

    const int lr = tid >> 1;
    const int lc = (tid & 1) * 8;
    const float* Ap = A + (size_t)(m0 + lr) * DIM + lc;
    const float* Wp = W + (size_t)(n0 + lr) * DIM + lc;

    float acc[2][8][4];
#pragma unroll
    for (int mt = 0; mt < 2; mt++)
#pragma unroll
        for (int nt = 0; nt < 8; nt++)
#pragma unroll
            for (int c = 0; c < 4; c++) acc[mt][nt][c] = 0.f;

    {
        float4 a0 = *(const float4*)Ap, a1 = *(const float4*)(Ap + 4);
        float4 b0 = *(const float4*)Wp, b1 = *(const float4*)(Wp + 4);
        *(float4*)&As[0][lr][lc]     = cvt4(a0);
        *(float4*)&As[0][lr][lc + 4] = cvt4(a1);
        *(float4*)&Bs[0][lr][lc]     = cvt4(b0);
        *(float4*)&Bs[0][lr][lc + 4] = cvt4(b1);
    }
    __syncthreads();

    for (int kt = 0; kt < 64; kt++) {
        const uint32_t bo = (kt & 1) ? 10240u : 0u;
        float4 pa0, pa1, pb0, pb1;
        if (kt < 63) {
            const float* s1 = Ap + (kt + 1) * 16;
            const float* s2 = Wp + (kt + 1) * 16;
            pa0 = *(const float4*)s1; pa1 = *(const float4*)(s1 + 4);
            pb0 = *(const float4*)s2; pb1 = *(const float4*)(s2 + 4);
        }
#pragma unroll
        for (int kc = 0; kc < 2; kc++) {
            uint32_t af[2][4], bf[4][4];
            ldsm4(af[0], aA + bo + kc * 32u);
            ldsm4(af[1], aA + bo + 1280u + kc * 32u);
#pragma unroll
            for (int p = 0; p < 4; p++)
                ldsm4(bf[p], aB + bo + (uint32_t)p * 1280u + kc * 32u);
#pragma unroll
            for (int mt = 0; mt < 2; mt++)
#pragma unroll
                for (int p = 0; p < 4; p++) {
                    mma8(acc[mt][2 * p],     af[mt], &bf[p][0]);
                    mma8(acc[mt][2 * p + 1], af[mt], &bf[p][2]);
                }
        }
        if (kt < 63) {
            const uint32_t nxt = (kt & 1) ^ 1;
            *(float4*)&As[nxt][lr][lc]     = cvt4(pa0);
            *(float4*)&As[nxt][lr][lc + 4] = cvt4(pa1);
            *(float4*)&Bs[nxt][lr][lc]     = cvt4(pb0);
            *(float4*)&Bs[nxt][lr][lc + 4] = cvt4(pb1);
        }
        __syncthreads();
    }

#pragma unroll
    for (int mt = 0; mt < 2; mt++) {
        const int r0 = m0 + wm + mt * 16 + g;
        const int r1 = r0 + 8;
#pragma unroll
        for (int nt = 0; nt < 8; nt++) {
            const int n = n0 + wn + nt * 8 + tq * 2;
            if (LAYOUT == 0) {
                const float b0v = bias[n], b1v = bias[n + 1];
                float2 v0 = make_float2(acc[mt][nt][0] + b0v, acc[mt][nt][1] + b1v);
                float2 v1 = make_float2(acc[mt][nt][2] + b0v, acc[mt][nt][3] + b1v);
                *(float2*)&C[(size_t)r0 * DIM + n] = v0;
                *(float2*)&C[(size_t)r1 * DIM + n] = v1;
            } else {
                const int h = n >> 6, d = n & 63;
                const int b0i = r0 >> 11, s0 = r0 & (NSEQ - 1);
                const int b1i = r1 >> 11, s1 = r1 & (NSEQ - 1);
                float2 v0 = make_float2(
                    __uint_as_float(f2tf32(acc[mt][nt][0] * scale)),
                    __uint_as_float(f2tf32(acc[mt][nt][1] * scale)));
                float2 v1 = make_float2(
                    __uint_as_float(f2tf32(acc[mt][nt][2] * scale)),
                    __uint_as_float(f2tf32(acc[mt][nt][3] * scale)));
                *(float2*)&C[((size_t)(b0i * NH + h) * NSEQ + s0) * DH + d] = v0;
                *(float2*)&C[((size_t)(b1i * NH + h) * NSEQ + s1) * DH + d] = v1;
            }
        }
    }
}

// ---------------------------------------------------------------------------
// Flash attention on tensor cores.  (R5 version — 284us measured)
// Bq=128 (4 warps x 2 m-tiles x 16 rows), Bk=64, Dh=64.
// Scalar fragment loads; Q fragments hoisted to registers; P overlays Q buffer.
// ---------------------------------------------------------------------------
#define AQP 0                   // Q staging, then P: [128][68]
#define AK  8704
#define AV  13056               // Ks: 64*68
#define AM  17664               // Vs: 64*72
#define ATTN_SMEM_BYTES ((17664 + 64) * 4)   // 70912

__global__ __launch_bounds__(128)
void attn_kernel(const float* __restrict__ Qg, const float* __restrict__ Kg,
                 const float* __restrict__ Vg, const int* __restrict__ mask,
                 float* __restrict__ Og)
{
    extern __shared__ float sm[];
    float* QPs = sm + AQP;  // [128][68]  (Q staging -> P)
    float* Ks  = sm + AK;   // [64][68]
    float* Vs  = sm + AV;   // [64][72]
    int*   mk  = (int*)(sm + AM);

    const int tid = threadIdx.x;
    const int lane = tid & 31, w = tid >> 5;
    const int g = lane >> 2, tq = lane & 3;
    const int bh = blockIdx.y;
    const int b = bh >> 4, h = bh & 15;
    const int q0 = blockIdx.x * 128;

    // stage Q tile (contiguous 128x64 block) into padded smem
    {
        const float* Qb = Qg + ((size_t)bh * NSEQ + q0) * DH;
#pragma unroll
        for (int it = 0; it < 16; it++) {
            int j = it * 128 + tid;                       // float4 index
            *(float4*)&QPs[(j >> 4) * 68 + (j & 15) * 4] = *(const float4*)(Qb + j * 4);
        }
    }
    __syncthreads();

    const int rb[2] = { w * 32 + g, w * 32 + 16 + g };    // base rows per m-tile

    // hoist Q fragments (loop-invariant) into registers; QPs rows rb[*] are
    // warp-private, so the buffer can be reused for P afterwards.
    uint32_t qf[2][8][4];
#pragma unroll
    for (int mt = 0; mt < 2; mt++)
#pragma unroll
        for (int kc = 0; kc < 8; kc++) {
            const int k0 = kc * 8;
            qf[mt][kc][0] = __float_as_uint(QPs[(rb[mt]    ) * 68 + k0 + tq    ]);
            qf[mt][kc][1] = __float_as_uint(QPs[(rb[mt] + 8) * 68 + k0 + tq    ]);
            qf[mt][kc][2] = __float_as_uint(QPs[(rb[mt]    ) * 68 + k0 + tq + 4]);
            qf[mt][kc][3] = __float_as_uint(QPs[(rb[mt] + 8) * 68 + k0 + tq + 4]);
        }

    float m_[2][2], l_[2][2], o[2][8][4];
#pragma unroll
    for (int mt = 0; mt < 2; mt++) {
        m_[mt][0] = -1e30f; m_[mt][1] = -1e30f;
        l_[mt][0] = 0.f;    l_[mt][1] = 0.f;
#pragma unroll
        for (int nt = 0; nt < 8; nt++)
#pragma unroll
            for (int c = 0; c < 4; c++) o[mt][nt][c] = 0.f;
    }

    for (int t = 0; t < NSEQ / 64; t++) {
        const int kv0 = t * 64;
        __syncthreads();
        {
            const float* Kb = Kg + ((size_t)bh * NSEQ + kv0) * DH;
            const float* Vb = Vg + ((size_t)bh * NSEQ + kv0) * DH;
#pragma unroll
            for (int it = 0; it < 8; it++) {
                int j = it * 128 + tid;                   // float4 index (64*16)
                *(float4*)&Ks[(j >> 4) * 68 + (j & 15) * 4] = *(const float4*)(Kb + j * 4);
                *(float4*)&Vs[(j >> 4) * 72 + (j & 15) * 4] = *(const float4*)(Vb + j * 4);
            }
            if (tid < 64) mk[tid] = mask[b * NSEQ + kv0 + tid];
        }
        __syncthreads();

        // S = Q @ K^T  (2 x 16 q-rows per warp x 64 kv)
        float s[2][8][4];
#pragma unroll
        for (int mt = 0; mt < 2; mt++)
#pragma unroll
            for (int nt = 0; nt < 8; nt++)
#pragma unroll
                for (int c = 0; c < 4; c++) s[mt][nt][c] = 0.f;

#pragma unroll
        for (int kc = 0; kc < 8; kc++) {
            const int k0 = kc * 8;
            uint32_t bf[8][2];
#pragma unroll
            for (int nt = 0; nt < 8; nt++) {
                bf[nt][0] = __float_as_uint(Ks[(nt * 8 + g) * 68 + k0 + tq    ]);
                bf[nt][1] = __float_as_uint(Ks[(nt * 8 + g) * 68 + k0 + tq + 4]);
            }
#pragma unroll
            for (int mt = 0; mt < 2; mt++)
#pragma unroll
                for (int nt = 0; nt < 8; nt++)
                    mma8(s[mt][nt], qf[mt][kc], bf[nt]);
        }

        // mask (per kv column)
#pragma unroll
        for (int nt = 0; nt < 8; nt++) {
            const int j = nt * 8 + tq * 2;
            const int mv0 = mk[j], mv1 = mk[j + 1];
#pragma unroll
            for (int mt = 0; mt < 2; mt++) {
                if (!mv0) { s[mt][nt][0] = -1e9f; s[mt][nt][2] = -1e9f; }
                if (!mv1) { s[mt][nt][1] = -1e9f; s[mt][nt][3] = -1e9f; }
            }
        }

        // online softmax (per m-tile, rows g and g+8; reduce across quad lanes)
#pragma unroll
        for (int mt = 0; mt < 2; mt++) {
            float rm0 = -1e30f, rm1 = -1e30f;
#pragma unroll
            for (int nt = 0; nt < 8; nt++) {
                rm0 = fmaxf(rm0, fmaxf(s[mt][nt][0], s[mt][nt][1]));
                rm1 = fmaxf(rm1, fmaxf(s[mt][nt][2], s[mt][nt][3]));
            }
            rm0 = fmaxf(rm0, __shfl_xor_sync(0xffffffffu, rm0, 1));
            rm0 = fmaxf(rm0, __shfl_xor_sync(0xffffffffu, rm0, 2));
            rm1 = fmaxf(rm1, __shfl_xor_sync(0xffffffffu, rm1, 1));
            rm1 = fmaxf(rm1, __shfl_xor_sync(0xffffffffu, rm1, 2));
            const float mn0 = fmaxf(m_[mt][0], rm0), mn1 = fmaxf(m_[mt][1], rm1);
            const float al0 = __expf(m_[mt][0] - mn0), al1 = __expf(m_[mt][1] - mn1);
            float rs0 = 0.f, rs1 = 0.f;
#pragma unroll
            for (int nt = 0; nt < 8; nt++) {
                s[mt][nt][0] = __expf(s[mt][nt][0] - mn0);
                s[mt][nt][1] = __expf(s[mt][nt][1] - mn0);
                s[mt][nt][2] = __expf(s[mt][nt][2] - mn1);
                s[mt][nt][3] = __expf(s[mt][nt][3] - mn1);
                rs0 += s[mt][nt][0] + s[mt][nt][1];
                rs1 += s[mt][nt][2] + s[mt][nt][3];
            }
            rs0 += __shfl_xor_sync(0xffffffffu, rs0, 1);
            rs0 += __shfl_xor_sync(0xffffffffu, rs0, 2);
            rs1 += __shfl_xor_sync(0xffffffffu, rs1, 1);
            rs1 += __shfl_xor_sync(0xffffffffu, rs1, 2);
            l_[mt][0] = l_[mt][0] * al0 + rs0;  m_[mt][0] = mn0;
            l_[mt][1] = l_[mt][1] * al1 + rs1;  m_[mt][1] = mn1;
#pragma unroll
            for (int nt = 0; nt < 8; nt++) {
                o[mt][nt][0] *= al0; o[mt][nt][1] *= al0;
                o[mt][nt][2] *= al1; o[mt][nt][3] *= al1;
            }
        }

        // write P (tf32) to warp-private rows of QPs
#pragma unroll
        for (int mt = 0; mt < 2; mt++)
#pragma unroll
            for (int nt = 0; nt < 8; nt++) {
                const int j = nt * 8 + tq * 2;
                float2 p0 = make_float2(__uint_as_float(f2tf32(s[mt][nt][0])),
                                        __uint_as_float(f2tf32(s[mt][nt][1])));
                float2 p1 = make_float2(__uint_as_float(f2tf32(s[mt][nt][2])),
                                        __uint_as_float(f2tf32(s[mt][nt][3])));
                *(float2*)&QPs[(rb[mt]    ) * 68 + j] = p0;
                *(float2*)&QPs[(rb[mt] + 8) * 68 + j] = p1;
            }
        __syncwarp();

        // O += P @ V   (k = 64 kv, n = 64 d)
#pragma unroll
        for (int kc = 0; kc < 8; kc++) {
            const int k0 = kc * 8;
            uint32_t af[2][4], bf[8][2];
#pragma unroll
            for (int mt = 0; mt < 2; mt++) {
                af[mt][0] = __float_as_uint(QPs[(rb[mt]    ) * 68 + k0 + tq    ]);
                af[mt][1] = __float_as_uint(QPs[(rb[mt] + 8) * 68 + k0 + tq    ]);
                af[mt][2] = __float_as_uint(QPs[(rb[mt]    ) * 68 + k0 + tq + 4]);
                af[mt][3] = __float_as_uint(QPs[(rb[mt] + 8) * 68 + k0 + tq + 4]);
            }
#pragma unroll
            for (int nt = 0; nt < 8; nt++) {
                bf[nt][0] = __float_as_uint(Vs[(k0 + tq    ) * 72 + nt * 8 + g]);
                bf[nt][1] = __float_as_uint(Vs[(k0 + tq + 4) * 72 + nt * 8 + g]);
            }
#pragma unroll
            for (int mt = 0; mt < 2; mt++)
#pragma unroll
                for (int nt = 0; nt < 8; nt++)
                    mma8(o[mt][nt], af[mt], bf[nt]);
        }
    }

    // final normalize + store
#pragma unroll
    for (int mt = 0; mt < 2; mt++) {
        const float inv0 = 1.f / l_[mt][0], inv1 = 1.f / l_[mt][1];
        const int qr0 = q0 + rb[mt], qr1 = qr0 + 8;
#pragma unroll
        for (int nt = 0; nt < 8; nt++) {
            const int d = nt * 8 + tq * 2;
            float2 v0 = make_float2(o[mt][nt][0] * inv0, o[mt][nt][1] * inv0);
            float2 v1 = make_float2(o[mt][nt][2] * inv1, o[mt][nt][3] * inv1);
            *(float2*)&Og[(size_t)(b * NSEQ + qr0) * DIM + h * DH + d] = v0;
            *(float2*)&Og[(size_t)(b * NSEQ + qr1) * DIM + h * DH + d] = v1;
        }
    }
}

// ---------------------------------------------------------------------------
extern "C" void kernel_launch(void* const* d_in, const int* in_sizes, int n_in,
                              void* d_out, int out_size)
{
    const float* x1 = (const float*)d_in[0];   // feat1_query
    const float* x2 = (const float*)d_in[1];   // feat2_key_value
    const float* Wq = (const float*)d_in[2];
    const float* Wk = (const float*)d_in[3];
    const float* Wv = (const float*)d_in[4];
    const float* Wo = (const float*)d_in[5];
    const float* bo = (const float*)d_in[6];
    const int*   mk = (const int*)d_in[7];
    float* out = (float*)d_out;

    float *q, *k, *v, *a;
    cudaGetSymbolAddress((void**)&q, g_Q);
    cudaGetSymbolAddress((void**)&k, g_K);
    cudaGetSymbolAddress((void**)&v, g_V);
    cudaGetSymbolAddress((void**)&a, g_A);

    const dim3 gg(DIM / 128, MTOK / 128);   // (8, 32)
    tgemm<2><<<gg, 256>>>(x1, Wq, nullptr, q, 0.125f);
    tgemm<2><<<gg, 256>>>(x2, Wk, nullptr, k, 1.0f);
    tgemm<2><<<gg, 256>>>(x2, Wv, nullptr, v, 1.0f);

    cudaFuncSetAttribute(attn_kernel, cudaFuncAttributeMaxDynamicSharedMemorySize,
                         ATTN_SMEM_BYTES);
    attn_kernel<<<dim3(NSEQ / 128, BATCH * NH), 128, ATTN_SMEM_BYTES>>>(q, k, v, mk, a);

    tgemm<0><<<gg, 256>>>(a, Wo, bo, out, 1.0f);
}